// round 4
// baseline (speedup 1.0000x reference)
#include <cuda_runtime.h>
#include <cuda_bf16.h>

// Problem constants
#define NB 32            // N
#define MODES 4
#define EYS 192          // EY_SIZE
#define EY_PLANE (EYS*EYS)          // 36864 floats
#define EY_PLANE4 (EY_PLANE/4)      // 9216 float4
#define EYROW4 (EYS/4)              // 48 float4 per Ey row
#define TOTAL 1184       // (N + 2*KNN + 1) * OUT_RES
#define NK (NB*NB)       // 1024

// Scratch: precomputed weights w[k][m] = U * neff*N0/(neff+N0), laid out [k*4+m]
__device__ float g_w[NK * MODES];

__global__ void compute_weights_kernel(const float* __restrict__ U,
                                       const float* __restrict__ neff) {
    int idx = blockIdx.x * blockDim.x + threadIdx.x;
    if (idx < NK * MODES) {
        float nf = neff[idx];
        float eta = nf * 1.5f / (nf + 1.5f);
        g_w[idx] = eta * U[idx];
    }
}

// One thread per (row r, 4-column group). j-loop is a COMPILE-TIME 6-trip
// unrolled loop: invalid slots clamp to a safe duplicate address (L1 hit)
// with weight forced to zero. 24 independent LDG.128 per i-iteration.
// blockDim = (32, 8); grid = (10, 148).
__global__ __launch_bounds__(256) void gather_en_kernel(
    const float* __restrict__ Ey,
    float* __restrict__ out)
{
    const int lane = threadIdx.x;
    const int r    = blockIdx.y * 8 + threadIdx.y;     // 0..1183, uniform per warp
    const int c    = blockIdx.x * 128 + lane * 4;      // 16B-aligned column
    const bool active = (c < TOTAL);
    const int cc   = active ? c : (TOTAL - 4);         // safe clamped column

    // i-range uniform per warp
    int i_lo = (r - 160) >> 5; if (i_lo < 0) i_lo = 0;
    int i_hi = r >> 5;         if (i_hi > NB - 1) i_hi = NB - 1;

    // j-range per lane (on clamped column)
    int j_lo = (cc - 160) >> 5; if (j_lo < 0) j_lo = 0;
    int j_hi = cc >> 5;         if (j_hi > NB - 1) j_hi = NB - 1;

    const float4* __restrict__ w4  = reinterpret_cast<const float4*>(g_w);
    const float4* __restrict__ Ey4 = reinterpret_cast<const float4*>(Ey);
    const float4 zero = make_float4(0.f, 0.f, 0.f, 0.f);

    float4 acc = zero;

    for (int i = i_lo; i <= i_hi; ++i) {
        const int x = r - (i << 5);                    // 0..191
        const long base_i = (long)(i << 5) * (MODES * EY_PLANE4) + (long)x * EYROW4;

        #pragma unroll
        for (int t = 0; t < 6; t += 2) {
            // slot A = t, slot B = t+1  (8 independent loads per step)
            const int jcA = j_hi - t;
            const int jcB = j_hi - t - 1;
            const bool vA = (jcA >= j_lo) && active;
            const bool vB = (jcB >= j_lo) && active;
            const int jA = vA ? jcA : j_lo;            // safe duplicate when invalid
            const int jB = vB ? jcB : j_lo;

            const float4* pA = Ey4 + base_i + (long)jA * (MODES * EY_PLANE4)
                                   + ((cc - (jA << 5)) >> 2);
            const float4* pB = Ey4 + base_i + (long)jB * (MODES * EY_PLANE4)
                                   + ((cc - (jB << 5)) >> 2);

            float4 wA = __ldg(&w4[(i << 5) + jA]);
            float4 wB = __ldg(&w4[(i << 5) + jB]);
            if (!vA) wA = zero;
            if (!vB) wB = zero;

            const float4 a0 = __ldg(pA);
            const float4 a1 = __ldg(pA + EY_PLANE4);
            const float4 a2 = __ldg(pA + 2 * EY_PLANE4);
            const float4 a3 = __ldg(pA + 3 * EY_PLANE4);
            const float4 b0 = __ldg(pB);
            const float4 b1 = __ldg(pB + EY_PLANE4);
            const float4 b2 = __ldg(pB + 2 * EY_PLANE4);
            const float4 b3 = __ldg(pB + 3 * EY_PLANE4);

            acc.x += wA.x * a0.x + wA.y * a1.x + wA.z * a2.x + wA.w * a3.x;
            acc.y += wA.x * a0.y + wA.y * a1.y + wA.z * a2.y + wA.w * a3.y;
            acc.z += wA.x * a0.z + wA.y * a1.z + wA.z * a2.z + wA.w * a3.z;
            acc.w += wA.x * a0.w + wA.y * a1.w + wA.z * a2.w + wA.w * a3.w;

            acc.x += wB.x * b0.x + wB.y * b1.x + wB.z * b2.x + wB.w * b3.x;
            acc.y += wB.x * b0.y + wB.y * b1.y + wB.z * b2.y + wB.w * b3.y;
            acc.z += wB.x * b0.z + wB.y * b1.z + wB.z * b2.z + wB.w * b3.z;
            acc.w += wB.x * b0.w + wB.y * b1.w + wB.z * b2.w + wB.w * b3.w;
        }
    }

    if (active) {
        *reinterpret_cast<float4*>(out + (long)r * TOTAL + c) = acc;
    }
}

extern "C" void kernel_launch(void* const* d_in, const int* in_sizes, int n_in,
                              void* d_out, int out_size) {
    // Inputs (metadata order): hs (unused), U, neff, Ey
    const float* U    = (const float*)d_in[1];
    const float* neff = (const float*)d_in[2];
    const float* Ey   = (const float*)d_in[3];
    float* out = (float*)d_out;

    compute_weights_kernel<<<(NK * MODES + 255) / 256, 256>>>(U, neff);

    dim3 block(32, 8);
    dim3 grid((TOTAL + 127) / 128, TOTAL / 8);   // (10, 148)
    gather_en_kernel<<<grid, block>>>(Ey, out);
}